// round 14
// baseline (speedup 1.0000x reference)
#include <cuda_runtime.h>

#define NE      262144      // edges
#define NMAT_SH 13          // log2(8192)
#define EPSV    1e-8f

#define NBLOCKS  128
#define NTHREADS 128
#define EPT      16                      // edges/thread; 128*128*16 == NE exactly
#define EPB      (NTHREADS * EPT)        // 2048 edges per block

#define FXSCALE 16777216.0               // 2^24 fixed-point scale

// Deterministic integer accumulator + completion ticket (device globals).
__device__ unsigned long long g_acc;     // zero-init; reset by last block
__device__ unsigned int       g_count;

// 4-byte async gather: global -> shared, tracked by commit-group (no register
// scoreboard, no per-warp LDG depth cap -> maximal DRAM queue occupancy).
__device__ __forceinline__ void cp4(unsigned int smem_addr, const float* gptr) {
    asm volatile("cp.async.ca.shared.global [%0], [%1], 4;"
                 :: "r"(smem_addr), "l"(gptr));
}

__global__ void __launch_bounds__(NTHREADS, 1)
fused_loss_kernel(const float* __restrict__ adj,
                  const int*   __restrict__ edge_index,   // [2, E]
                  const int*   __restrict__ neg_edges,    // [E, 2]
                  const float* __restrict__ codebook,
                  float*       __restrict__ out)
{
    // smem gather buffer: [2*EPT][NTHREADS] floats -> conflict-free readback
    __shared__ float s_val[2 * EPT][NTHREADS];

    const int tid = threadIdx.x;
    const int bid = blockIdx.x;
    const int e0  = bid * EPB + EPT * tid;   // this thread: edges e0..e0+15

    // ---- Phase 1: coalesced vector index loads ----
    int4 s4[4], d4[4], n4[8];
#pragma unroll
    for (int k = 0; k < 4; k++) {
        s4[k] = __ldg((const int4*)&edge_index[e0 + 4 * k]);
        d4[k] = __ldg((const int4*)&edge_index[NE + e0 + 4 * k]);
    }
#pragma unroll
    for (int k = 0; k < 8; k++)
        n4[k] = __ldg((const int4*)&neg_edges[2 * e0 + 4 * k]);

    // ---- Phase 2: issue ALL 32 gathers as cp.async (deep in-flight window) ----
    unsigned int sbase;
    asm("{ .reg .u64 t; cvta.to.shared.u64 t, %1; cvt.u32.u64 %0, t; }"
        : "=r"(sbase) : "l"(&s_val[0][tid]));
    const unsigned int stride = NTHREADS * 4;   // bytes between k rows

    const int* s = (const int*)s4;
    const int* d = (const int*)d4;
    const int* n = (const int*)n4;
#pragma unroll
    for (int k = 0; k < EPT; k++)
        cp4(sbase + k * stride, &adj[(s[k] << NMAT_SH) + d[k]]);
#pragma unroll
    for (int k = 0; k < EPT; k++)
        cp4(sbase + (EPT + k) * stride, &adj[(n[2*k] << NMAT_SH) + n[2*k + 1]]);

    asm volatile("cp.async.commit_group;" ::: "memory");
    asm volatile("cp.async.wait_group 0;" ::: "memory");

    // ---- Phase 3: fold 32 terms into EIGHT logs (each 4-term product in [1e-32,1]) ----
    float acc = 0.f;
#pragma unroll
    for (int g = 0; g < 4; g++) {
        float pr = ((s_val[4*g+0][tid] + EPSV) * (s_val[4*g+1][tid] + EPSV))
                 * ((s_val[4*g+2][tid] + EPSV) * (s_val[4*g+3][tid] + EPSV));
        float qr = ((1.0f - s_val[EPT+4*g+0][tid] + EPSV) * (1.0f - s_val[EPT+4*g+1][tid] + EPSV))
                 * ((1.0f - s_val[EPT+4*g+2][tid] + EPSV) * (1.0f - s_val[EPT+4*g+3][tid] + EPSV));
        acc += __logf(pr) + __logf(qr);
    }

    // ---- Phase 4: warp + block reduction ----
#pragma unroll
    for (int off = 16; off > 0; off >>= 1)
        acc += __shfl_down_sync(0xFFFFFFFFu, acc, off);

    __shared__ float s_acc[NTHREADS / 32];
    const int lane = tid & 31;
    const int wid  = tid >> 5;
    if (lane == 0) s_acc[wid] = acc;
    __syncthreads();

    if (tid == 0) {
        double dsum = 0.0;
#pragma unroll
        for (int w = 0; w < NTHREADS / 32; w++) dsum += (double)s_acc[w];

        // Exact, order-independent integer accumulation (deterministic).
        atomicAdd(&g_acc, (unsigned long long)llrint(dsum * FXSCALE));
        __threadfence();
        unsigned int ticket = atomicAdd(&g_count, 1u);

        // ---- Phase 5: last block finalizes (tiny tail) ----
        if (ticket == NBLOCKS - 1) {
            unsigned long long u = atomicAdd(&g_acc, 0ULL);   // strong read
            double total = (double)(long long)u / FXSCALE;
            double loss  = -total / (double)NE
                         + (double)codebook[0] + (double)codebook[1]
                         + (double)codebook[2] + (double)codebook[3];
            out[0] = (float)loss;
            // Reset scratch for next graph replay (stream-ordered).
            g_acc = 0ULL;
            __threadfence();
            g_count = 0;
        }
    }
}

extern "C" void kernel_launch(void* const* d_in, const int* in_sizes, int n_in,
                              void* d_out, int out_size)
{
    const float* adj        = (const float*)d_in[0];   // [N*N] fp32
    const float* codebook   = (const float*)d_in[1];   // [6] fp32
    const int*   edge_index = (const int*)d_in[2];     // [2*E] int32
    const int*   neg_edges  = (const int*)d_in[3];     // [E*2] int32
    float* out = (float*)d_out;

    fused_loss_kernel<<<NBLOCKS, NTHREADS>>>(adj, edge_index, neg_edges, codebook, out);
}